// round 6
// baseline (speedup 1.0000x reference)
#include <cuda_runtime.h>

#define DIM     4096
#define HALF    2048
#define NLAYERS 12

// Per-pair rotation constants: th = tan(theta/2), ns = -sin(theta).
// Rotation [[c,s],[-s,c]] as 3 shears: xa += th*xb; xb += ns*xa; xa += th*xb;
__device__ float g_th[NLAYERS * HALF];
__device__ float g_ns[NLAYERS * HALF];

__global__ void prep_kernel(const float* __restrict__ angles) {
    int i = blockIdx.x * blockDim.x + threadIdx.x;
    if (i < NLAYERS * HALF) {
        float s, c;
        sincosf(angles[i], &s, &c);
        g_ns[i] = -s;
        g_th[i] = s / (1.0f + c);
    }
}

// Swizzle for 64-bit smem words: injects bits[4:6] into bits[0:2] and bit6 into
// bit3. Bijective on [0,4096). Conflict-free (distinct idx mod 16 per 16-lane
// phase) for all four exchange patterns used below.
__device__ __forceinline__ int SW(int e) {
    return e ^ ((e >> 4) & 7) ^ ((e >> 3) & 8);
}

typedef unsigned long long u64;

__device__ __forceinline__ u64 pack2(float v) {
    u64 r; unsigned int u = __float_as_uint(v);
    asm("mov.b64 %0, {%1,%1};" : "=l"(r) : "r"(u));
    return r;
}
__device__ __forceinline__ u64 packab(float a, float b) {
    u64 r;
    asm("mov.b64 %0, {%1,%2};" : "=l"(r)
        : "r"(__float_as_uint(a)), "r"(__float_as_uint(b)));
    return r;
}
__device__ __forceinline__ u64 fma2(u64 a, u64 b, u64 c) {
    u64 d;
    asm("fma.rn.f32x2 %0, %1, %2, %3;" : "=l"(d) : "l"(a), "l"(b), "l"(c));
    return d;
}
__device__ __forceinline__ void unpack2(u64 v, float& lo, float& hi) {
    unsigned int a, b;
    asm("mov.b64 {%0,%1}, %2;" : "=r"(a), "=r"(b) : "l"(v));
    lo = __uint_as_float(a); hi = __uint_as_float(b);
}

// 3 butterfly layers on 8 packed (2-row) elements, 3 FMA2 per pair.
__device__ __forceinline__ void bf3p(u64 x[8], const float (&th)[3][4], const float (&ns)[3][4]) {
#pragma unroll
    for (int lz = 0; lz < 3; lz++) {
        const int sig = 1 << lz;
#pragma unroll
        for (int k = 0; k < 4; k++) {
            const int a = ((k >> lz) << (lz + 1)) | (k & (sig - 1));
            const int b = a + sig;
            u64 t2 = pack2(th[lz][k]);
            u64 n2 = pack2(ns[lz][k]);
            x[a] = fma2(t2, x[b], x[a]);
            x[b] = fma2(n2, x[a], x[b]);
            x[a] = fma2(t2, x[b], x[a]);
        }
    }
}

extern __shared__ u64 sb_dyn[];   // 3 * DIM u64 = 96 KB

__global__ __launch_bounds__(512, 1)
void butterfly_kernel(const float* __restrict__ X, float* __restrict__ Y, int npairs) {
    const int t = threadIdx.x;
    u64* A = sb_dyn;
    u64* B = sb_dyn + DIM;
    u64* C = sb_dyn + 2 * DIM;

    // ---- one-time per-CTA constant gather (amortized over ~27 iterations) ----
    float tt[4][3][4], nn[4][3][4];
#pragma unroll
    for (int ph = 0; ph < 4; ph++) {
#pragma unroll
        for (int lz = 0; lz < 3; lz++) {
#pragma unroll
            for (int k = 0; k < 4; k++) {
                const int sig = 1 << lz;
                const int j = ((k >> lz) << (lz + 1)) | (k & (sig - 1));
                int e;
                if      (ph == 0) e = 8 * t + j;
                else if (ph == 1) e = 64 * (t >> 3) + 8 * j + (t & 7);
                else if (ph == 2) e = 512 * (t >> 6) + 64 * j + (t & 63);
                else              e = 512 * j + t;
                const int l = ph * 3 + lz;
                const int p = ((e >> (l + 1)) << l) | (e & ((1 << l) - 1));
                tt[ph][lz][k] = g_th[l * HALF + p];
                nn[ph][lz][k] = g_ns[l * HALF + p];
            }
        }
    }

    const int b1 = 64 * (t >> 3) + (t & 7);    // phase-1 base (stride 8)
    const int b2 = 512 * (t >> 6) + (t & 63);  // phase-2 base (stride 64)

    // ---- persistent loop over row-pairs ----
    for (int p = blockIdx.x; p < npairs; p += gridDim.x) {
        const float* r0 = X + (size_t)(2 * p) * DIM + 8 * t;
        const float4 u0 = ((const float4*)r0)[0];
        const float4 u1 = ((const float4*)r0)[1];
        const float4 v0 = ((const float4*)(r0 + DIM))[0];
        const float4 v1 = ((const float4*)(r0 + DIM))[1];

        u64 x[8];
        x[0] = packab(u0.x, v0.x); x[1] = packab(u0.y, v0.y);
        x[2] = packab(u0.z, v0.z); x[3] = packab(u0.w, v0.w);
        x[4] = packab(u1.x, v1.x); x[5] = packab(u1.y, v1.y);
        x[6] = packab(u1.z, v1.z); x[7] = packab(u1.w, v1.w);

        // register-free L2 prefetch of the next row-pair (1 thread per 128B line)
        const int np_ = p + gridDim.x;
        if ((t & 3) == 0 && np_ < npairs) {
            const char* q = (const char*)(X + (size_t)(2 * np_) * DIM + 8 * t);
            asm volatile("prefetch.global.L2 [%0];" :: "l"(q));
            asm volatile("prefetch.global.L2 [%0];" :: "l"(q + DIM * 4));
        }

        // phase 0: layers 0..2 (strides 1,2,4)
        bf3p(x, tt[0], nn[0]);
#pragma unroll
        for (int j = 0; j < 8; j++) A[SW(8 * t + j)] = x[j];
        __syncthreads();
#pragma unroll
        for (int j = 0; j < 8; j++) x[j] = A[SW(b1 + 8 * j)];

        // phase 1: layers 3..5 (strides 8,16,32)
        bf3p(x, tt[1], nn[1]);
#pragma unroll
        for (int j = 0; j < 8; j++) B[SW(b1 + 8 * j)] = x[j];
        __syncthreads();
#pragma unroll
        for (int j = 0; j < 8; j++) x[j] = B[SW(b2 + 64 * j)];

        // phase 2: layers 6..8 (strides 64,128,256)
        bf3p(x, tt[2], nn[2]);
#pragma unroll
        for (int j = 0; j < 8; j++) C[SW(b2 + 64 * j)] = x[j];
        __syncthreads();
#pragma unroll
        for (int j = 0; j < 8; j++) x[j] = C[SW(512 * j + t)];

        // phase 3: layers 9..11 (strides 512,1024,2048)
        bf3p(x, tt[3], nn[3]);

        // stores: element 512*j + t, both rows -> coalesced 128B per warp
        float* y0 = Y + (size_t)(2 * p) * DIM + t;
        float* y1 = y0 + DIM;
#pragma unroll
        for (int j = 0; j < 8; j++) {
            float lo, hi;
            unpack2(x[j], lo, hi);
            y0[512 * j] = lo;
            y1[512 * j] = hi;
        }
        // No trailing sync needed: iteration i+1's store-A is ordered after this
        // iteration's syncs 2 and 3, which dominate every thread's last A read.
    }
}

extern "C" void kernel_launch(void* const* d_in, const int* in_sizes, int n_in,
                              void* d_out, int out_size) {
    const float* x      = (const float*)d_in[0];
    const float* angles = (const float*)d_in[1];
    float* y = (float*)d_out;

    const int batch  = in_sizes[0] / DIM;
    const int npairs = batch / 2;      // batch = 8192, even

    int nsm = 148;
    cudaDeviceGetAttribute(&nsm, cudaDevAttrMultiProcessorCount, 0);

    static int smem_set = 0;
    const int smem_bytes = 3 * DIM * (int)sizeof(u64);   // 96 KB
    if (!smem_set) {
        cudaFuncSetAttribute(butterfly_kernel,
                             cudaFuncAttributeMaxDynamicSharedMemorySize, smem_bytes);
        smem_set = 1;
    }

    prep_kernel<<<(NLAYERS * HALF + 511) / 512, 512>>>(angles);
    butterfly_kernel<<<nsm, 512, smem_bytes>>>(x, y, npairs);
}